// round 1
// baseline (speedup 1.0000x reference)
#include <cuda_runtime.h>
#include <cuda/atomic>

#define NSEQ 16384
#define HDIM 512
#define GDIM 2048
#define NCTA 128
#define TPB  256

// Scratch (device globals: no allocation allowed)
__device__ float g_XE[(size_t)NSEQ * GDIM];   // encoder x-part, bias folded
__device__ float g_XD[(size_t)NSEQ * GDIM];   // decoder x-part rows 1..N-1, bias folded
__device__ float g_h[2 * HDIM];               // double-buffered hidden state
__device__ unsigned int g_bar;                // monotonic grid barrier counter

// ---------------------------------------------------------------------------
// init: zero h0 and barrier counter (graph-capture-safe, no memset/symbol API)
// ---------------------------------------------------------------------------
__global__ void init_kernel() {
    int t = threadIdx.x;
    if (t < 2 * HDIM) g_h[t] = 0.f;
    if (t == 0) g_bar = 0u;
}

// ---------------------------------------------------------------------------
// GEMM: OUT[m][n] = sum_k A[m][ak(k)] * W[n][k] + b1[n] + b2[n]
// A: [M,512] row-major (x). FLIP reverses A's feature index (decoder input).
// FLIP also selects destination: g_XD+GDIM (rows 1..N-1), else g_XE.
// BM=BN=128, BK=16, 256 threads, 8x8 microtile.
// ---------------------------------------------------------------------------
template <bool FLIP>
__global__ __launch_bounds__(256, 2) void gemm_xpart(
    const float* __restrict__ A, const float* __restrict__ W,
    const float* __restrict__ b1, const float* __restrict__ b2, int Mlim)
{
    __shared__ float As[16][132];
    __shared__ float Ws[16][132];
    float* OUT = FLIP ? (g_XD + GDIM) : g_XE;

    const int bn = blockIdx.x, bm = blockIdx.y;
    const int tid = threadIdx.x;
    const int tx = tid & 15, ty = tid >> 4;

    float acc[8][8];
#pragma unroll
    for (int i = 0; i < 8; i++)
#pragma unroll
        for (int j = 0; j < 8; j++) acc[i][j] = 0.f;

    for (int k0 = 0; k0 < 512; k0 += 16) {
        // Load A tile (transposed into As[k][m])
#pragma unroll
        for (int l = 0; l < 2; l++) {
            int fid = tid + l * 256;
            int r = fid >> 2, c4 = fid & 3;
            int gm = bm * 128 + r;
            float4 v = make_float4(0.f, 0.f, 0.f, 0.f);
            if (gm < Mlim) {
                if (!FLIP) {
                    v = *(const float4*)(A + (size_t)gm * 512 + k0 + c4 * 4);
                } else {
                    float4 w = *(const float4*)(A + (size_t)gm * 512 + (508 - k0 - c4 * 4));
                    v = make_float4(w.w, w.z, w.y, w.x);
                }
            }
            As[c4 * 4 + 0][r] = v.x; As[c4 * 4 + 1][r] = v.y;
            As[c4 * 4 + 2][r] = v.z; As[c4 * 4 + 3][r] = v.w;
        }
        // Load W tile (transposed into Ws[k][n])
#pragma unroll
        for (int l = 0; l < 2; l++) {
            int fid = tid + l * 256;
            int r = fid >> 2, c4 = fid & 3;
            int gn = bn * 128 + r;
            float4 v = *(const float4*)(W + (size_t)gn * 512 + k0 + c4 * 4);
            Ws[c4 * 4 + 0][r] = v.x; Ws[c4 * 4 + 1][r] = v.y;
            Ws[c4 * 4 + 2][r] = v.z; Ws[c4 * 4 + 3][r] = v.w;
        }
        __syncthreads();
#pragma unroll
        for (int k = 0; k < 16; k++) {
            float ra[8], rb[8];
#pragma unroll
            for (int i = 0; i < 8; i++) ra[i] = As[k][ty * 8 + i];
#pragma unroll
            for (int j = 0; j < 8; j++) rb[j] = Ws[k][tx * 8 + j];
#pragma unroll
            for (int i = 0; i < 8; i++)
#pragma unroll
                for (int j = 0; j < 8; j++) acc[i][j] = fmaf(ra[i], rb[j], acc[i][j]);
        }
        __syncthreads();
    }

    // Epilogue: add bias, coalesced float4 stores
    float bj[8];
#pragma unroll
    for (int j = 0; j < 8; j++) {
        int gn = bn * 128 + tx * 8 + j;
        bj[j] = b1[gn] + b2[gn];
    }
#pragma unroll
    for (int i = 0; i < 8; i++) {
        int gm = bm * 128 + ty * 8 + i;
        if (gm < Mlim) {
            float* o = OUT + (size_t)gm * GDIM + bn * 128 + tx * 8;
            float4 v0 = make_float4(acc[i][0] + bj[0], acc[i][1] + bj[1],
                                    acc[i][2] + bj[2], acc[i][3] + bj[3]);
            float4 v1 = make_float4(acc[i][4] + bj[4], acc[i][5] + bj[5],
                                    acc[i][6] + bj[6], acc[i][7] + bj[7]);
            *(float4*)(o) = v0;
            *(float4*)(o + 4) = v1;
        }
    }
}

// ---------------------------------------------------------------------------
// Persistent recurrent scan: 128 CTAs (one wave), Whh in registers.
// CTA c owns hidden units [4c, 4c+4). Thread t: local row li=t/16 (gate=li/4,
// unit=li%4), k-segment seg=t%16 covering 32 of the 512 h elements.
// ---------------------------------------------------------------------------
__device__ __forceinline__ float sigm_(float x) { return 1.f / (1.f + __expf(-x)); }
__device__ __forceinline__ float tanh_(float x) { return 2.f / (1.f + __expf(-2.f * x)) - 1.f; }

__global__ __launch_bounds__(TPB, 1) void lstm_scan(
    const float* __restrict__ Whh_e, const float* __restrict__ Whh_d,
    const float* __restrict__ Wih_d, const float* __restrict__ bih_d,
    const float* __restrict__ bhh_d, float* __restrict__ out)
{
    const int cta = blockIdx.x;
    const int t = threadIdx.x;
    const int li = t >> 4, seg = t & 15;
    const int gate = li >> 2, u = li & 3;
    const int grow = gate * HDIM + cta * 4 + u;   // global gate-row in [0,2048)

    // Recurrent weights: 32 enc + 32 dec floats per thread, in registers.
    float we[32], wd[32];
    {
        const float4* pe = (const float4*)(Whh_e + (size_t)grow * HDIM + seg * 32);
        const float4* pd = (const float4*)(Whh_d + (size_t)grow * HDIM + seg * 32);
#pragma unroll
        for (int i = 0; i < 8; i++) {
            float4 a = pe[i];
            we[4 * i] = a.x; we[4 * i + 1] = a.y; we[4 * i + 2] = a.z; we[4 * i + 3] = a.w;
            float4 b = pd[i];
            wd[4 * i] = b.x; wd[4 * i + 1] = b.y; wd[4 * i + 2] = b.z; wd[4 * i + 3] = b.w;
        }
    }

    __shared__ float sh[HDIM];
    __shared__ float sred[16];
    __shared__ float sx[16];

    float c = 0.f;  // cell state, valid in lanes t<4 (unit = t)

    const int pg = t >> 2, pu = t & 3;            // x-part prefetch mapping (t<16)
    const int pcol = pg * HDIM + cta * 4 + pu;

    cuda::atomic_ref<unsigned int, cuda::thread_scope_device> bar(g_bar);

#pragma unroll 1
    for (int step = 1; step <= 2 * NSEQ; ++step) {
        const bool dec = step > NSEQ;
        const int s = dec ? step - NSEQ : step;
        const bool xd0 = dec && (s == 1);

        // Prefetch x-part for this step (independent of h; overlaps the spin)
        float xv = 0.f;
        if (t < 16 && !xd0) {
            const float* xb = dec ? (g_XD + (size_t)(s - 1) * GDIM)
                                  : (g_XE + (size_t)(s - 1) * GDIM);
            xv = __ldg(xb + pcol);
        }

        // Grid barrier: wait until all CTAs published h_{step-1}
        if (t == 0 && step > 1) {
            const unsigned int target = (unsigned int)NCTA * (unsigned int)(step - 1);
            while (bar.load(cuda::memory_order_acquire) < target) { }
        }
        __syncthreads();

        // Load h_{step-1} into SMEM (L2-fresh via .cg)
        const float* hb = g_h + ((step - 1) & 1) * HDIM;
        if (t < 128) {
            float4 hv = __ldcg((const float4*)hb + t);
            ((float4*)sh)[t] = hv;
        }
        if (t < 16) sx[t] = xv;
        __syncthreads();

        // Partial dot: 32 MACs against register weights
        float a0 = 0.f, a1 = 0.f, a2 = 0.f, a3 = 0.f;
        const float4* sh4 = (const float4*)sh + seg * 8;
        if (!dec) {
#pragma unroll
            for (int i = 0; i < 8; i++) {
                float4 h4 = sh4[i];
                a0 = fmaf(we[4 * i], h4.x, a0);
                a1 = fmaf(we[4 * i + 1], h4.y, a1);
                a2 = fmaf(we[4 * i + 2], h4.z, a2);
                a3 = fmaf(we[4 * i + 3], h4.w, a3);
            }
        } else {
#pragma unroll
            for (int i = 0; i < 8; i++) {
                float4 h4 = sh4[i];
                a0 = fmaf(wd[4 * i], h4.x, a0);
                a1 = fmaf(wd[4 * i + 1], h4.y, a1);
                a2 = fmaf(wd[4 * i + 2], h4.z, a2);
                a3 = fmaf(wd[4 * i + 3], h4.w, a3);
            }
        }
        float sum = (a0 + a1) + (a2 + a3);

        // Decoder step 1: input is h_n itself -> add Wih_d . h_n inline
        if (xd0) {
            const float4* pw = (const float4*)(Wih_d + (size_t)grow * HDIM + seg * 32);
            float c0 = 0.f, c1 = 0.f, c2 = 0.f, c3 = 0.f;
#pragma unroll
            for (int i = 0; i < 8; i++) {
                float4 w4 = pw[i];
                float4 h4 = sh4[i];
                c0 = fmaf(w4.x, h4.x, c0);
                c1 = fmaf(w4.y, h4.y, c1);
                c2 = fmaf(w4.z, h4.z, c2);
                c3 = fmaf(w4.w, h4.w, c3);
            }
            sum += (c0 + c1) + (c2 + c3);
        }

        // Reduce over 16 k-segments (two independent 16-lane halves per warp)
        sum += __shfl_xor_sync(0xffffffffu, sum, 1);
        sum += __shfl_xor_sync(0xffffffffu, sum, 2);
        sum += __shfl_xor_sync(0xffffffffu, sum, 4);
        sum += __shfl_xor_sync(0xffffffffu, sum, 8);
        if (seg == 0) sred[li] = sum;
        __syncthreads();

        // Lanes 0..3 (unit u = t): gates -> c,h update -> publish
        if (t < 4) {
            float xi = sx[t], xf = sx[4 + t], xg = sx[8 + t], xo = sx[12 + t];
            if (xd0) {  // bias not folded for the locally-computed row 0
                int base = cta * 4 + t;
                xi = __ldg(bih_d + base)        + __ldg(bhh_d + base);
                xf = __ldg(bih_d + 512 + base)  + __ldg(bhh_d + 512 + base);
                xg = __ldg(bih_d + 1024 + base) + __ldg(bhh_d + 1024 + base);
                xo = __ldg(bih_d + 1536 + base) + __ldg(bhh_d + 1536 + base);
            }
            float gi = sigm_(sred[t] + xi);
            float gf = sigm_(sred[4 + t] + xf);
            float gg = tanh_(sred[8 + t] + xg);
            float go = sigm_(sred[12 + t] + xo);
            c = fmaf(gf, c, gi * gg);
            float hn = go * tanh_(c);

            const int j = cta * 4 + t;
            g_h[(step & 1) * HDIM + j] = hn;
            if (dec) {
                out[HDIM + (size_t)(s - 1) * HDIM + (HDIM - 1 - j)] = hn;  // feature flip
            } else if (step == NSEQ) {
                out[j] = hn;  // h_n
            }
        }
        __syncthreads();
        if (t == 0) bar.fetch_add(1u, cuda::memory_order_release);
    }
}

// ---------------------------------------------------------------------------
extern "C" void kernel_launch(void* const* d_in, const int* in_sizes, int n_in,
                              void* d_out, int out_size)
{
    const float* x     = (const float*)d_in[0];
    const float* Wih_e = (const float*)d_in[1];
    const float* Whh_e = (const float*)d_in[2];
    const float* bih_e = (const float*)d_in[3];
    const float* bhh_e = (const float*)d_in[4];
    const float* Wih_d = (const float*)d_in[5];
    const float* Whh_d = (const float*)d_in[6];
    const float* bih_d = (const float*)d_in[7];
    const float* bhh_d = (const float*)d_in[8];
    float* out = (float*)d_out;

    init_kernel<<<1, 1024>>>();

    dim3 gg(GDIM / 128, NSEQ / 128);
    gemm_xpart<false><<<gg, 256>>>(x, Wih_e, bih_e, bhh_e, NSEQ);
    gemm_xpart<true ><<<gg, 256>>>(x, Wih_d, bih_d, bhh_d, NSEQ - 1);

    lstm_scan<<<NCTA, TPB>>>(Whh_e, Whh_d, Wih_d, bih_d, bhh_d, out);
}